// round 2
// baseline (speedup 1.0000x reference)
#include <cuda_runtime.h>
#include <math.h>

// Problem constants (match reference)
#define BATCH   256
#define IN_DIM  512
#define OUT_DIM 512
#define KORD    3
#define GN      23   // grid points per input dim (NUM + 2K + 1)
#define NB      19   // number of basis functions (NUM + K)

// Main-kernel tiling
#define OTILE   32
#define NSPLIT  16
#define ICHUNK  (IN_DIM / NSPLIT)   // 32

// Scratch (no cudaMalloc allowed -> __device__ globals)
__device__ float4 g_w4[IN_DIM * BATCH];     // 4 nonzero basis weights per (i,b)
__device__ float  g_base[IN_DIM * BATCH];   // silu(x) per (i,b)
__device__ int    g_jidx[IN_DIM * BATCH];   // window start index per (i,b)
__device__ float  g_part[NSPLIT * OUT_DIM * BATCH]; // split-i partial sums

// ---------------------------------------------------------------------------
// Kernel 1: per-(b,i) prep — silu base + sparse cubic B-spline basis.
// block = one input dim i (grid row cached in smem), threads = batch.
// ---------------------------------------------------------------------------
__global__ void kan_prep_kernel(const float* __restrict__ x,
                                const float* __restrict__ grid)
{
    __shared__ float G[GN];
    const int i = blockIdx.x;
    const int b = threadIdx.x;
    if (threadIdx.x < GN) G[threadIdx.x] = grid[i * GN + threadIdx.x];
    __syncthreads();

    const float xv = x[b * IN_DIM + i];

    // silu
    const float base = xv / (1.0f + __expf(-xv));

    // order-0 interval: g[m] <= x < g[m+1]
    int m = -1;
    #pragma unroll
    for (int t = 0; t < GN - 1; t++) {
        if (xv >= G[t] && xv < G[t + 1]) m = t;
    }

    float w0 = 0.f, w1 = 0.f, w2 = 0.f, w3 = 0.f;
    int j = 0;

    if (m >= 0) {
        // Cox–de Boor on the 4-wide local support. arr[s] = B_{m-kk+s}^{kk}.
        float arr[4] = {1.0f, 0.0f, 0.0f, 0.0f};
        #pragma unroll
        for (int kk = 1; kk <= KORD; kk++) {
            float nxt[4] = {0.f, 0.f, 0.f, 0.f};
            #pragma unroll
            for (int s = 0; s <= KORD; s++) {
                if (s > kk) break;
                const int r = m - kk + s;
                // clamped grid access: out-of-range slots are discarded below,
                // and never feed a kept slot (support recursion is one-sided).
                auto gg = [&](int idx) -> float {
                    idx = idx < 0 ? 0 : (idx > GN - 1 ? GN - 1 : idx);
                    return G[idx];
                };
                float v = 0.0f;
                if (s >= 1) {
                    const float den = gg(r + kk) - gg(r);
                    if (den != 0.0f) v += (xv - gg(r)) / den * arr[s - 1];
                }
                if (s < kk) {
                    const float den = gg(r + kk + 1) - gg(r + 1);
                    if (den != 0.0f) v += (gg(r + kk + 1) - xv) / den * arr[s];
                }
                nxt[s] = v;
            }
            #pragma unroll
            for (int s = 0; s < 4; s++) arr[s] = nxt[s];
        }
        // Nonzero final basis indices: r in [m-3, m] ∩ [0, NB-1].
        // Shift into a window starting at j = clamp(m-3, 0, NB-4).
        j = m - KORD;
        if (j < 0) j = 0;
        if (j > NB - 4) j = NB - 4;
        float w[4];
        #pragma unroll
        for (int t = 0; t < 4; t++) {
            const int r = j + t;
            const bool valid = (r >= m - KORD) && (r <= m) && (r >= 0) && (r <= NB - 1);
            w[t] = valid ? arr[r - (m - KORD)] : 0.0f;
        }
        w0 = w[0]; w1 = w[1]; w2 = w[2]; w3 = w[3];
    }

    const int idx = i * BATCH + b;
    g_w4[idx]   = make_float4(w0, w1, w2, w3);
    g_base[idx] = base;
    g_jidx[idx] = j;
}

// ---------------------------------------------------------------------------
// Kernel 2: main contraction over i (split into NSPLIT chunks for occupancy).
// block: 256 threads = 256 batches; OTILE outputs; ICHUNK input dims.
// coef tile lives in smem padded to 20 floats/row -> window loads [j..j+3]
// span <=19 consecutive words (<32 banks) => conflict-free despite per-lane j.
// ---------------------------------------------------------------------------
__global__ __launch_bounds__(BATCH) void kan_main_kernel(
    const float* __restrict__ coef,
    const float* __restrict__ scale_sp,
    const float* __restrict__ mask)
{
    __shared__ float cs[OTILE * 20];
    __shared__ float msc_s[OTILE];   // mask * scale_sp
    __shared__ float mk_s[OTILE];    // mask

    const int o0    = blockIdx.x * OTILE;
    const int split = blockIdx.y;
    const int t     = threadIdx.x;   // batch index

    float acc[OTILE];
    #pragma unroll
    for (int o = 0; o < OTILE; o++) acc[o] = 0.0f;

    for (int ii = 0; ii < ICHUNK; ii++) {
        const int i = split * ICHUNK + ii;
        __syncthreads();
        // coef[i, o0:o0+OTILE, 0:19] is a contiguous 608-float block in gmem
        {
            const float* src = coef + ((size_t)i * OUT_DIM + o0) * NB;
            for (int k = t; k < OTILE * NB; k += BATCH) {
                const int orow = k / NB;
                const int g    = k - orow * NB;
                cs[orow * 20 + g] = src[k];
            }
            if (t < OTILE) {
                const float s = scale_sp[i * OUT_DIM + o0 + t];
                const float m = mask[i * OUT_DIM + o0 + t];
                msc_s[t] = s * m;
                mk_s[t]  = m;
            }
        }
        __syncthreads();

        const int idx = i * BATCH + t;
        const float4 w   = g_w4[idx];
        const float  bse = g_base[idx];
        const int    j   = g_jidx[idx];
        const float* cp  = cs + j;

        #pragma unroll
        for (int o = 0; o < OTILE; o++) {
            const float c0 = cp[o * 20 + 0];
            const float c1 = cp[o * 20 + 1];
            const float c2 = cp[o * 20 + 2];
            const float c3 = cp[o * 20 + 3];
            const float dot = w.x * c0 + w.y * c1 + w.z * c2 + w.w * c3;
            acc[o] += mk_s[o] * bse + msc_s[o] * dot;
        }
    }

    // partials laid out [split][o][b] so lane stores are coalesced
    float* dst = g_part + ((size_t)split * OUT_DIM + o0) * BATCH + t;
    #pragma unroll
    for (int o = 0; o < OTILE; o++) dst[o * BATCH] = acc[o];
}

// ---------------------------------------------------------------------------
// Kernel 3: deterministic reduction over the NSPLIT partials.
// ---------------------------------------------------------------------------
__global__ void kan_reduce_kernel(float* __restrict__ out)
{
    const int idx = blockIdx.x * blockDim.x + threadIdx.x; // 131072 threads
    const int b = idx & (BATCH - 1);
    const int o = idx >> 8;
    float s = 0.0f;
    #pragma unroll
    for (int sp = 0; sp < NSPLIT; sp++) {
        s += g_part[((size_t)sp * OUT_DIM + o) * BATCH + b];
    }
    out[b * OUT_DIM + o] = s;
}

// ---------------------------------------------------------------------------
// Launch. Inputs (metadata order): x, grid, coef, scale_sp, mask. Output fp32.
// ---------------------------------------------------------------------------
extern "C" void kernel_launch(void* const* d_in, const int* in_sizes, int n_in,
                              void* d_out, int out_size)
{
    const float* x        = (const float*)d_in[0];
    const float* grid     = (const float*)d_in[1];
    const float* coef     = (const float*)d_in[2];
    const float* scale_sp = (const float*)d_in[3];
    const float* mask     = (const float*)d_in[4];
    float* out = (float*)d_out;

    kan_prep_kernel<<<IN_DIM, BATCH>>>(x, grid);

    dim3 grid2(OUT_DIM / OTILE, NSPLIT);
    kan_main_kernel<<<grid2, BATCH>>>(coef, scale_sp, mask);

    kan_reduce_kernel<<<(BATCH * OUT_DIM) / 256, 256>>>(out);
}

// round 4
// speedup vs baseline: 1.1816x; 1.1816x over previous
#include <cuda_runtime.h>
#include <math.h>

// Problem constants (match reference)
#define BATCH   256
#define IN_DIM  512
#define OUT_DIM 512
#define KORD    3
#define GN      23   // grid points per input dim
#define NB      19   // number of basis functions

// Main-kernel tiling
#define OTILE   32
#define OPAIRS  (OTILE / 2)          // 16
#define NSPLIT  32
#define ICHUNK  (IN_DIM / NSPLIT)    // 16
#define NI      8                    // i's per smem slab

typedef unsigned long long ull;

// Scratch (no cudaMalloc allowed -> __device__ globals)
__device__ float4 g_w4[IN_DIM * BATCH];
__device__ float  g_base[IN_DIM * BATCH];
__device__ int    g_jidx[IN_DIM * BATCH];
__device__ float  g_part[NSPLIT * OUT_DIM * BATCH];

// ---- f32x2 helpers ---------------------------------------------------------
__device__ __forceinline__ ull fma2(ull a, ull b, ull c) {
    ull d;
    asm("fma.rn.f32x2 %0, %1, %2, %3;" : "=l"(d) : "l"(a), "l"(b), "l"(c));
    return d;
}
__device__ __forceinline__ ull pack2(float x) {
    ull d;
    asm("mov.b64 %0, {%1, %1};" : "=l"(d) : "f"(x));
    return d;
}
__device__ __forceinline__ void unpack2(ull v, float& lo, float& hi) {
    asm("mov.b64 {%0, %1}, %2;" : "=f"(lo), "=f"(hi) : "l"(v));
}

// ---------------------------------------------------------------------------
// Kernel 1: prep — tiled (32 i x 32 b), coalesced x reads via smem transpose.
// grid: (IN_DIM/32, BATCH/32), block 256 threads.
// ---------------------------------------------------------------------------
__global__ __launch_bounds__(256) void kan_prep_kernel(
    const float* __restrict__ x,
    const float* __restrict__ grid)
{
    __shared__ float xs[32][33];   // [i_local][b_local]
    __shared__ float Gs[32][24];   // [i_local][g]

    const int i0 = blockIdx.x * 32;
    const int b0 = blockIdx.y * 32;
    const int tid = threadIdx.x;
    const int lane = tid & 31;     // column
    const int row  = tid >> 5;     // 0..7

    // load x tile coalesced: x[b0+r][i0+lane]
    #pragma unroll
    for (int p = 0; p < 4; p++) {
        const int r = row + p * 8;
        xs[lane][r] = x[(size_t)(b0 + r) * IN_DIM + i0 + lane];
    }
    // load grid rows: grid[i0+r][g]
    #pragma unroll
    for (int p = 0; p < 4; p++) {
        const int r = row + p * 8;
        if (lane < GN) Gs[r][lane] = grid[(size_t)(i0 + r) * GN + lane];
    }
    __syncthreads();

    // compute: lane = b_local, (row + 8p) = i_local
    #pragma unroll
    for (int p = 0; p < 4; p++) {
        const int il = row + p * 8;
        const float xv = xs[il][lane];
        const float* G = Gs[il];

        const float base = xv / (1.0f + __expf(-xv));

        int m = -1;
        #pragma unroll
        for (int t = 0; t < GN - 1; t++) {
            if (xv >= G[t] && xv < G[t + 1]) m = t;
        }

        float w0 = 0.f, w1 = 0.f, w2 = 0.f, w3 = 0.f;
        int j = 0;

        if (m >= 0) {
            float arr[4] = {1.0f, 0.0f, 0.0f, 0.0f};
            #pragma unroll
            for (int kk = 1; kk <= KORD; kk++) {
                float nxt[4] = {0.f, 0.f, 0.f, 0.f};
                #pragma unroll
                for (int s = 0; s <= KORD; s++) {
                    if (s > kk) break;
                    const int r = m - kk + s;
                    auto gg = [&](int idx) -> float {
                        idx = idx < 0 ? 0 : (idx > GN - 1 ? GN - 1 : idx);
                        return G[idx];
                    };
                    float v = 0.0f;
                    if (s >= 1) {
                        const float den = gg(r + kk) - gg(r);
                        if (den != 0.0f) v += (xv - gg(r)) / den * arr[s - 1];
                    }
                    if (s < kk) {
                        const float den = gg(r + kk + 1) - gg(r + 1);
                        if (den != 0.0f) v += (gg(r + kk + 1) - xv) / den * arr[s];
                    }
                    nxt[s] = v;
                }
                #pragma unroll
                for (int s = 0; s < 4; s++) arr[s] = nxt[s];
            }
            j = m - KORD;
            if (j < 0) j = 0;
            if (j > NB - 4) j = NB - 4;
            float w[4];
            #pragma unroll
            for (int t = 0; t < 4; t++) {
                const int r = j + t;
                const bool valid = (r >= m - KORD) && (r <= m) && (r >= 0) && (r <= NB - 1);
                w[t] = valid ? arr[r - (m - KORD)] : 0.0f;
            }
            w0 = w[0]; w1 = w[1]; w2 = w[2]; w3 = w[3];
        }

        const int idx = (i0 + il) * BATCH + b0 + lane;   // lane=b -> coalesced
        g_w4[idx]   = make_float4(w0, w1, w2, w3);
        g_base[idx] = base;
        g_jidx[idx] = j;
    }
}

// ---------------------------------------------------------------------------
// Kernel 2: main contraction. f32x2 over o-pairs; smem slab of NI i's.
// smem layout: cs[ii][o2][g*2 + parity]; scale*mask folded into coef values,
// raw mask stored at pad slot g=19. Window loads are LDS.64, conflict-free.
// ---------------------------------------------------------------------------
__global__ __launch_bounds__(256) void kan_main_kernel(
    const float* __restrict__ coef,
    const float* __restrict__ scale_sp,
    const float* __restrict__ mask)
{
    __shared__ float cs[NI][OPAIRS][40];   // 20 KB

    const int o0    = blockIdx.x * OTILE;
    const int split = blockIdx.y;
    const int t     = threadIdx.x;         // batch index

    ull acc[OPAIRS];
    #pragma unroll
    for (int o2 = 0; o2 < OPAIRS; o2++) acc[o2] = 0ULL;

    for (int slab = 0; slab < ICHUNK / NI; slab++) {
        const int ibase = split * ICHUNK + slab * NI;
        __syncthreads();

        // ---- load slab: coef * (scale*mask), pair-interleaved -------------
        for (int k = t; k < NI * OTILE * NB; k += 256) {
            const int ii  = k / (OTILE * NB);
            const int rem = k - ii * (OTILE * NB);
            const int o   = rem / NB;
            const int g   = rem - o * NB;
            const int i   = ibase + ii;
            const size_t io = (size_t)i * OUT_DIM + o0 + o;
            const float msc = scale_sp[io] * mask[io];
            cs[ii][o >> 1][g * 2 + (o & 1)] = coef[io * NB + g] * msc;
        }
        // mask at pad slot g=19
        if (t < NI * OTILE) {
            const int ii = t / OTILE;
            const int o  = t - ii * OTILE;
            const int i  = ibase + ii;
            cs[ii][o >> 1][38 + (o & 1)] = mask[(size_t)i * OUT_DIM + o0 + o];
        }
        __syncthreads();

        // ---- compute NI i's ----------------------------------------------
        #pragma unroll
        for (int ii = 0; ii < NI; ii++) {
            const int idx = (ibase + ii) * BATCH + t;
            const float4 w   = g_w4[idx];
            const float  bse = g_base[idx];
            const int    j   = g_jidx[idx];

            const ull w0p = pack2(w.x);
            const ull w1p = pack2(w.y);
            const ull w2p = pack2(w.z);
            const ull w3p = pack2(w.w);
            const ull bsp = pack2(bse);

            const ull* rowbase = (const ull*)&cs[ii][0][0];
            #pragma unroll
            for (int o2 = 0; o2 < OPAIRS; o2++) {
                const ull* row = rowbase + o2 * 20;
                const ull c0 = row[j];
                const ull c1 = row[j + 1];
                const ull c2 = row[j + 2];
                const ull c3 = row[j + 3];
                const ull mk = row[19];       // broadcast (lane-uniform addr)
                ull a = acc[o2];
                a = fma2(w0p, c0, a);
                a = fma2(w1p, c1, a);
                a = fma2(w2p, c2, a);
                a = fma2(w3p, c3, a);
                a = fma2(mk,  bsp, a);
                acc[o2] = a;
            }
        }
    }

    // partials: [split][o][b], coalesced stores
    float* dst = g_part + ((size_t)split * OUT_DIM + o0) * BATCH + t;
    #pragma unroll
    for (int o2 = 0; o2 < OPAIRS; o2++) {
        float lo, hi;
        unpack2(acc[o2], lo, hi);
        dst[(2 * o2)     * BATCH] = lo;
        dst[(2 * o2 + 1) * BATCH] = hi;
    }
}

// ---------------------------------------------------------------------------
// Kernel 3: reduction over NSPLIT partials with smem transpose so both the
// partial reads and the output writes are coalesced.
// grid: (OUT_DIM/32, BATCH/32), block 256.
// ---------------------------------------------------------------------------
__global__ __launch_bounds__(256) void kan_reduce_kernel(float* __restrict__ out)
{
    __shared__ float ts[32][33];   // [o_local][b_local]

    const int o0 = blockIdx.x * 32;
    const int b0 = blockIdx.y * 32;
    const int tid = threadIdx.x;
    const int lane = tid & 31;
    const int row  = tid >> 5;

    #pragma unroll
    for (int p = 0; p < 4; p++) {
        const int ol = row + p * 8;
        float s = 0.0f;
        #pragma unroll
        for (int sp = 0; sp < NSPLIT; sp++) {
            s += g_part[((size_t)sp * OUT_DIM + o0 + ol) * BATCH + b0 + lane];
        }
        ts[ol][lane] = s;
    }
    __syncthreads();
    #pragma unroll
    for (int p = 0; p < 4; p++) {
        const int bl = row + p * 8;
        out[(size_t)(b0 + bl) * OUT_DIM + o0 + lane] = ts[lane][bl];
    }
}

// ---------------------------------------------------------------------------
// Launch. Inputs: x, grid, coef, scale_sp, mask. Output fp32 [BATCH, OUT_DIM].
// ---------------------------------------------------------------------------
extern "C" void kernel_launch(void* const* d_in, const int* in_sizes, int n_in,
                              void* d_out, int out_size)
{
    const float* x        = (const float*)d_in[0];
    const float* grid     = (const float*)d_in[1];
    const float* coef     = (const float*)d_in[2];
    const float* scale_sp = (const float*)d_in[3];
    const float* mask     = (const float*)d_in[4];
    float* out = (float*)d_out;

    dim3 gp(IN_DIM / 32, BATCH / 32);
    kan_prep_kernel<<<gp, 256>>>(x, grid);

    dim3 gm(OUT_DIM / OTILE, NSPLIT);
    kan_main_kernel<<<gm, 256>>>(coef, scale_sp, mask);

    dim3 gr(OUT_DIM / 32, BATCH / 32);
    kan_reduce_kernel<<<gr, 256>>>(out);
}

// round 5
// speedup vs baseline: 1.6601x; 1.4050x over previous
#include <cuda_runtime.h>
#include <math.h>

// Problem constants (match reference)
#define BATCH   256
#define IN_DIM  512
#define OUT_DIM 512
#define KORD    3
#define GN      23   // grid points per input dim
#define NB      19   // number of basis functions

// Main-kernel tiling
#define OTILE   32
#define OPAIRS  (OTILE / 2)          // 16
#define NSPLIT  32
#define ICHUNK  (IN_DIM / NSPLIT)    // 16
#define NI      ICHUNK               // one slab per block
#define RS      22                   // smem row stride in 32-bit words

// Scratch (no cudaMalloc allowed -> __device__ globals)
__device__ float4 g_w4[IN_DIM * BATCH];
__device__ float  g_base[IN_DIM * BATCH];
__device__ int    g_jidx[IN_DIM * BATCH];
__device__ float  g_part[NSPLIT * OUT_DIM * BATCH];

// ---------------------------------------------------------------------------
// Kernel 1: prep — one (b,i) task per thread. 512 blocks of 256 threads.
// block covers 32 i (lane) x 8 b (warp row). x read coalesced into registers.
// Gs stride 25 (gcd(25,32)=1) -> per-lane grid-row reads are conflict-free.
// ---------------------------------------------------------------------------
__global__ __launch_bounds__(256) void kan_prep_kernel(
    const float* __restrict__ x,
    const float* __restrict__ grid)
{
    __shared__ float Gs[32][25];

    const int i0 = blockIdx.x * 32;
    const int b0 = blockIdx.y * 8;
    const int t    = threadIdx.x;
    const int lane = t & 31;   // i_local
    const int row  = t >> 5;   // b_local

    for (int k = t; k < 32 * GN; k += 256) {
        const int r = k / GN, c = k - r * GN;
        Gs[r][c] = grid[(size_t)(i0 + r) * GN + c];
    }
    const float xv = x[(size_t)(b0 + row) * IN_DIM + i0 + lane];
    __syncthreads();

    const float* G = Gs[lane];
    const float base = xv / (1.0f + __expf(-xv));

    int m = -1;
    #pragma unroll
    for (int tt = 0; tt < GN - 1; tt++) {
        if (xv >= G[tt] && xv < G[tt + 1]) m = tt;
    }

    float w0 = 0.f, w1 = 0.f, w2 = 0.f, w3 = 0.f;
    int j = 0;

    if (m >= 0) {
        float arr[4] = {1.0f, 0.0f, 0.0f, 0.0f};
        #pragma unroll
        for (int kk = 1; kk <= KORD; kk++) {
            float nxt[4] = {0.f, 0.f, 0.f, 0.f};
            #pragma unroll
            for (int s = 0; s <= KORD; s++) {
                if (s > kk) break;
                const int r = m - kk + s;
                auto gg = [&](int idx) -> float {
                    idx = idx < 0 ? 0 : (idx > GN - 1 ? GN - 1 : idx);
                    return G[idx];
                };
                float v = 0.0f;
                if (s >= 1) {
                    const float den = gg(r + kk) - gg(r);
                    if (den != 0.0f) v += (xv - gg(r)) / den * arr[s - 1];
                }
                if (s < kk) {
                    const float den = gg(r + kk + 1) - gg(r + 1);
                    if (den != 0.0f) v += (gg(r + kk + 1) - xv) / den * arr[s];
                }
                nxt[s] = v;
            }
            #pragma unroll
            for (int s = 0; s < 4; s++) arr[s] = nxt[s];
        }
        j = m - KORD;
        if (j < 0) j = 0;
        if (j > NB - 4) j = NB - 4;
        float w[4];
        #pragma unroll
        for (int tt = 0; tt < 4; tt++) {
            const int r = j + tt;
            const bool valid = (r >= m - KORD) && (r <= m) && (r >= 0) && (r <= NB - 1);
            w[tt] = valid ? arr[r - (m - KORD)] : 0.0f;
        }
        w0 = w[0]; w1 = w[1]; w2 = w[2]; w3 = w[3];
    }

    const int idx = (i0 + lane) * BATCH + b0 + row;
    g_w4[idx]   = make_float4(w0, w1, w2, w3);
    g_base[idx] = base;
    g_jidx[idx] = j;
}

// ---------------------------------------------------------------------------
// Kernel 2: main contraction.
// smem word cs[ii][o2][g] = bf16x2( coef_odd*msc , coef_even*msc );
// mask stored as raw f32 at words 19/20 of each row. Window reads are 4
// conflict-free LDS.32 per (warp,i,o2). bf16->f32: hi = raw word, lo = word<<16.
// Fast path when all 32 masks of an i-row are exactly 1.0f: base accumulates
// into one o-independent scalar (warp-uniform branch, no divergence).
// ---------------------------------------------------------------------------
__global__ __launch_bounds__(256) void kan_main_kernel(
    const float* __restrict__ coef,
    const float* __restrict__ scale_sp,
    const float* __restrict__ mask)
{
    __shared__ unsigned cs[NI * OPAIRS * RS];   // 16*16*22 words = 22.5 KB
    __shared__ float    msc_s[NI * OTILE];      // 512 floats
    __shared__ int      flag_s[NI];

    const int o0    = blockIdx.x * OTILE;
    const int split = blockIdx.y;
    const int t     = threadIdx.x;              // batch index in compute phase
    const int ibase = split * ICHUNK;

    // ---- phase A: masks, msc, fast-path flags -----------------------------
    #pragma unroll
    for (int rr = 0; rr < (NI * OTILE) / 256; rr++) {
        const int id = t + rr * 256;
        const int ii = id >> 5;
        const int o  = id & 31;
        const size_t io = (size_t)(ibase + ii) * OUT_DIM + o0 + o;
        const float mk = mask[io];
        const float sc = scale_sp[io];
        msc_s[id] = mk * sc;
        ((float*)cs)[ii * (OPAIRS * RS) + (o >> 1) * RS + 19 + (o & 1)] = mk;
        const int all1 = __all_sync(0xffffffffu, mk == 1.0f);
        if ((t & 31) == 0) flag_s[ii] = all1;
    }
    __syncthreads();

    // ---- phase B: fold + convert coef to bf16x2 (4864 words = 19 iters) ---
    #pragma unroll
    for (int k = 0; k < 19; k++) {
        const int w   = t + k * 256;            // < 4864 exactly
        const int ii  = w / (OPAIRS * NB);      // /304
        const int rem = w - ii * (OPAIRS * NB);
        const int o2  = rem / NB;
        const int g   = rem - o2 * NB;
        const size_t ioE = (size_t)(ibase + ii) * OUT_DIM + o0 + 2 * o2;
        const float cE = coef[ioE * NB + g]       * msc_s[ii * 32 + 2 * o2];
        const float cO = coef[(ioE + 1) * NB + g] * msc_s[ii * 32 + 2 * o2 + 1];
        unsigned u;
        asm("cvt.rn.bf16x2.f32 %0, %1, %2;" : "=r"(u) : "f"(cO), "f"(cE));
        cs[ii * (OPAIRS * RS) + o2 * RS + g] = u;
    }
    __syncthreads();

    // ---- compute ----------------------------------------------------------
    float accE[OPAIRS], accO[OPAIRS];
    #pragma unroll
    for (int o2 = 0; o2 < OPAIRS; o2++) { accE[o2] = 0.f; accO[o2] = 0.f; }
    float sb = 0.0f;   // fast-path base accumulator (o-independent)

    for (int ii = 0; ii < NI; ii++) {
        const int idx = (ibase + ii) * BATCH + t;
        const float4 wv  = g_w4[idx];
        const float  bse = g_base[idx];
        const int    j   = g_jidx[idx];
        const unsigned* rowj = cs + ii * (OPAIRS * RS) + j;

        if (flag_s[ii]) {
            sb += bse;
            #pragma unroll
            for (int o2 = 0; o2 < OPAIRS; o2++) {
                const unsigned* r = rowj + o2 * RS;
                const unsigned u0 = r[0], u1 = r[1], u2 = r[2], u3 = r[3];
                float e = accE[o2], od = accO[o2];
                od = fmaf(wv.x, __uint_as_float(u0),       od);
                e  = fmaf(wv.x, __uint_as_float(u0 << 16), e);
                od = fmaf(wv.y, __uint_as_float(u1),       od);
                e  = fmaf(wv.y, __uint_as_float(u1 << 16), e);
                od = fmaf(wv.z, __uint_as_float(u2),       od);
                e  = fmaf(wv.z, __uint_as_float(u2 << 16), e);
                od = fmaf(wv.w, __uint_as_float(u3),       od);
                e  = fmaf(wv.w, __uint_as_float(u3 << 16), e);
                accE[o2] = e; accO[o2] = od;
            }
        } else {
            const float* rowm = (const float*)(cs + ii * (OPAIRS * RS));
            #pragma unroll
            for (int o2 = 0; o2 < OPAIRS; o2++) {
                const unsigned* r = rowj + o2 * RS;
                const unsigned u0 = r[0], u1 = r[1], u2 = r[2], u3 = r[3];
                float e = accE[o2], od = accO[o2];
                od = fmaf(wv.x, __uint_as_float(u0),       od);
                e  = fmaf(wv.x, __uint_as_float(u0 << 16), e);
                od = fmaf(wv.y, __uint_as_float(u1),       od);
                e  = fmaf(wv.y, __uint_as_float(u1 << 16), e);
                od = fmaf(wv.z, __uint_as_float(u2),       od);
                e  = fmaf(wv.z, __uint_as_float(u2 << 16), e);
                od = fmaf(wv.w, __uint_as_float(u3),       od);
                e  = fmaf(wv.w, __uint_as_float(u3 << 16), e);
                // exact fp32 mask * base (general path)
                e  = fmaf(rowm[o2 * RS + 19], bse, e);
                od = fmaf(rowm[o2 * RS + 20], bse, od);
                accE[o2] = e; accO[o2] = od;
            }
        }
    }

    // partials: [split][o][b], coalesced stores; sb applies to all o (mask==1)
    float* dst = g_part + ((size_t)split * OUT_DIM + o0) * BATCH + t;
    #pragma unroll
    for (int o2 = 0; o2 < OPAIRS; o2++) {
        dst[(2 * o2)     * BATCH] = accE[o2] + sb;
        dst[(2 * o2 + 1) * BATCH] = accO[o2] + sb;
    }
}

// ---------------------------------------------------------------------------
// Kernel 3: reduction over NSPLIT partials, coalesced both ways via transpose.
// ---------------------------------------------------------------------------
__global__ __launch_bounds__(256) void kan_reduce_kernel(float* __restrict__ out)
{
    __shared__ float ts[32][33];

    const int o0 = blockIdx.x * 32;
    const int b0 = blockIdx.y * 32;
    const int t    = threadIdx.x;
    const int lane = t & 31;
    const int row  = t >> 5;

    #pragma unroll
    for (int p = 0; p < 4; p++) {
        const int ol = row + p * 8;
        float s = 0.0f;
        #pragma unroll
        for (int sp = 0; sp < NSPLIT; sp++) {
            s += g_part[((size_t)sp * OUT_DIM + o0 + ol) * BATCH + b0 + lane];
        }
        ts[ol][lane] = s;
    }
    __syncthreads();
    #pragma unroll
    for (int p = 0; p < 4; p++) {
        const int bl = row + p * 8;
        out[(size_t)(b0 + bl) * OUT_DIM + o0 + lane] = ts[lane][bl];
    }
}

// ---------------------------------------------------------------------------
// Launch. Inputs: x, grid, coef, scale_sp, mask. Output fp32 [BATCH, OUT_DIM].
// ---------------------------------------------------------------------------
extern "C" void kernel_launch(void* const* d_in, const int* in_sizes, int n_in,
                              void* d_out, int out_size)
{
    const float* x        = (const float*)d_in[0];
    const float* grid     = (const float*)d_in[1];
    const float* coef     = (const float*)d_in[2];
    const float* scale_sp = (const float*)d_in[3];
    const float* mask     = (const float*)d_in[4];
    float* out = (float*)d_out;

    dim3 gp(IN_DIM / 32, BATCH / 8);
    kan_prep_kernel<<<gp, 256>>>(x, grid);

    dim3 gm(OUT_DIM / OTILE, NSPLIT);
    kan_main_kernel<<<gm, 256>>>(coef, scale_sp, mask);

    dim3 gr(OUT_DIM / 32, BATCH / 32);
    kan_reduce_kernel<<<gr, 256>>>(out);
}

// round 7
// speedup vs baseline: 1.8896x; 1.1382x over previous
#include <cuda_runtime.h>
#include <cuda_bf16.h>
#include <mma.h>
#include <math.h>
#include <stdint.h>

using namespace nvcuda;

// Problem constants
#define BATCH   256
#define IN_DIM  512
#define OUT_DIM 512
#define KORD    3
#define GN      23
#define NB      19

// GEMM geometry: K-slot per input dim = 24 -> Ktot = 512*24 = 12288
#define KSLOT   24
#define KTOT    (IN_DIM * KSLOT)        // 12288
#define MT      128
#define NT      128
#define KSPLIT  16
#define KLOCAL  (KTOT / KSPLIT)         // 768
#define KC      64                      // bf16 K per smem chunk
#define NCHUNK  (KLOCAL / KC)           // 12
#define RSW     72                      // smem row stride in bf16 (144B: LDSM conflict-free)

// Static device scratch (no allocations allowed)
__device__ __nv_bfloat16 g_Bmat [BATCH * KTOT];            // 6.3 MB
__device__ __nv_bfloat16 g_coefT[OUT_DIM * KTOT];          // 12.6 MB
__device__ float         g_part [KSPLIT * BATCH * OUT_DIM];// 8 MB

__device__ __forceinline__ uint32_t smem_u32(const void* p) {
    uint32_t a;
    asm("{ .reg .u64 t; cvta.to.shared.u64 t, %1; cvt.u32.u64 %0, t; }"
        : "=r"(a) : "l"(p));
    return a;
}
__device__ __forceinline__ void cp_async16(uint32_t dst, const void* src) {
    asm volatile("cp.async.cg.shared.global [%0], [%1], 16;" :: "r"(dst), "l"(src));
}

// ---------------------------------------------------------------------------
// Kernel 1: prep — silu + sparse cubic B-spline; writes dense Bmat rows.
// K-slots per i: [0..18]=basis (w at j..j+3), 19=0, 20=base_hi, 21=base_lo,
// 22,23=0.  grid (IN/32, BATCH/8), 256 threads; thread = (i=lane, b=row).
// ---------------------------------------------------------------------------
__global__ __launch_bounds__(256) void kan_prep_kernel(
    const float* __restrict__ x, const float* __restrict__ grid)
{
    __shared__ float Gs[32][25];
    __shared__ float rowbuf[256][25];

    const int i0 = blockIdx.x * 32;
    const int b0 = blockIdx.y * 8;
    const int t    = threadIdx.x;
    const int lane = t & 31;   // i_local
    const int row  = t >> 5;   // b_local

    for (int k = t; k < 32 * GN; k += 256) {
        const int r = k / GN, c = k - r * GN;
        Gs[r][c] = grid[(size_t)(i0 + r) * GN + c];
    }
    const float xv = x[(size_t)(b0 + row) * IN_DIM + i0 + lane];
    __syncthreads();

    const float* G = Gs[lane];
    const float base = xv / (1.0f + __expf(-xv));

    int m = -1;
    #pragma unroll
    for (int tt = 0; tt < GN - 1; tt++)
        if (xv >= G[tt] && xv < G[tt + 1]) m = tt;

    float w0 = 0.f, w1 = 0.f, w2 = 0.f, w3 = 0.f;
    int j = 0;
    if (m >= 0) {
        float arr[4] = {1.0f, 0.f, 0.f, 0.f};
        #pragma unroll
        for (int kk = 1; kk <= KORD; kk++) {
            float nxt[4] = {0.f, 0.f, 0.f, 0.f};
            #pragma unroll
            for (int s = 0; s <= KORD; s++) {
                if (s > kk) break;
                const int r = m - kk + s;
                auto gg = [&](int idx) -> float {
                    idx = idx < 0 ? 0 : (idx > GN - 1 ? GN - 1 : idx);
                    return G[idx];
                };
                float v = 0.0f;
                if (s >= 1) {
                    const float den = gg(r + kk) - gg(r);
                    if (den != 0.0f) v += (xv - gg(r)) / den * arr[s - 1];
                }
                if (s < kk) {
                    const float den = gg(r + kk + 1) - gg(r + 1);
                    if (den != 0.0f) v += (gg(r + kk + 1) - xv) / den * arr[s];
                }
                nxt[s] = v;
            }
            #pragma unroll
            for (int s = 0; s < 4; s++) arr[s] = nxt[s];
        }
        j = m - KORD;
        if (j < 0) j = 0;
        if (j > NB - 4) j = NB - 4;
        float w[4];
        #pragma unroll
        for (int tt = 0; tt < 4; tt++) {
            const int r = j + tt;
            const bool valid = (r >= m - KORD) && (r <= m) && (r >= 0) && (r <= NB - 1);
            w[tt] = valid ? arr[r - (m - KORD)] : 0.0f;
        }
        w0 = w[0]; w1 = w[1]; w2 = w[2]; w3 = w[3];
    }

    // base split: hi = bf16(base) (rn), lo = base - hi
    const float hi = __bfloat162float(__float2bfloat16(base));
    const float lo = base - hi;

    float* rb = rowbuf[t];
    #pragma unroll
    for (int s = 0; s < 19; s++) rb[s] = 0.0f;
    rb[j]     = w0;
    rb[j + 1] = w1;
    rb[j + 2] = w2;
    rb[j + 3] = w3;
    rb[19] = 0.0f; rb[20] = base; rb[21] = lo; rb[22] = 0.0f; rb[23] = 0.0f;

    unsigned uw[12];
    #pragma unroll
    for (int p = 0; p < 12; p++) {
        asm("cvt.rn.bf16x2.f32 %0, %1, %2;"
            : "=r"(uw[p]) : "f"(rb[2 * p + 1]), "f"(rb[2 * p]));
    }
    uint4* dst = (uint4*)((char*)g_Bmat + (size_t)(b0 + row) * (KTOT * 2)
                          + (size_t)(i0 + lane) * (KSLOT * 2));
    dst[0] = make_uint4(uw[0], uw[1], uw[2],  uw[3]);
    dst[1] = make_uint4(uw[4], uw[5], uw[6],  uw[7]);
    dst[2] = make_uint4(uw[8], uw[9], uw[10], uw[11]);
}

// ---------------------------------------------------------------------------
// Kernel 2: fold — coefT[o][i*24+g] = bf16(coef[i][o][g]*scale*mask); slots
// 19,22,23 = 0; 20,21 = bf16(mask). Tiles (16 i x 32 o).
// ---------------------------------------------------------------------------
__global__ __launch_bounds__(256) void kan_fold_kernel(
    const float* __restrict__ coef,
    const float* __restrict__ scale_sp,
    const float* __restrict__ mask)
{
    __shared__ float msc[16 * 32];
    __shared__ __align__(16) __nv_bfloat16 T[32][16 * KSLOT];   // 24 KB

    const int i0 = blockIdx.x * 16;
    const int o0 = blockIdx.y * 32;
    const int t  = threadIdx.x;

    #pragma unroll
    for (int rr = 0; rr < 2; rr++) {
        const int id = t + rr * 256;
        const int il = id >> 5, ol = id & 31;
        const size_t io = (size_t)(i0 + il) * OUT_DIM + o0 + ol;
        const float mk = mask[io];
        msc[id] = mk * scale_sp[io];
        const __nv_bfloat16 mb = __float2bfloat16(mk);
        const __nv_bfloat16 zb = __float2bfloat16(0.0f);
        T[ol][il * KSLOT + 19] = zb;
        T[ol][il * KSLOT + 20] = mb;
        T[ol][il * KSLOT + 21] = mb;
        T[ol][il * KSLOT + 22] = zb;
        T[ol][il * KSLOT + 23] = zb;
    }
    __syncthreads();

    #pragma unroll
    for (int k = 0; k < 38; k++) {
        const int lin = t + k * 256;            // < 9728 exactly
        const int il  = lin / 608;
        const int rem = lin - il * 608;
        const int ol  = rem / NB;
        const int g   = rem - ol * NB;
        const float v = coef[(size_t)(i0 + il) * (OUT_DIM * NB) + o0 * NB + rem]
                        * msc[il * 32 + ol];
        T[ol][il * KSLOT + g] = __float2bfloat16(v);
    }
    __syncthreads();

    const int ol  = t >> 3;
    const int sub = t & 7;
    uint4* dst = (uint4*)((char*)g_coefT + (size_t)(o0 + ol) * (KTOT * 2)
                          + (size_t)i0 * (KSLOT * 2));
    const uint4* src = (const uint4*)&T[ol][0];
    #pragma unroll
    for (int k = 0; k < 6; k++) dst[sub + k * 8] = src[sub + k * 8];
}

// ---------------------------------------------------------------------------
// Kernel 3: bf16 wmma (HMMA) GEMM with K-split.
// grid (2, 4, 16); 256 threads = 8 warps in 2(M) x 4(N); warp tile 64x32.
// Smem: double-buffered A/B chunks of 128 rows x KC bf16, row stride RSW=72
// (144B -> LDSM rows land on distinct bank quads, no swizzle needed).
// ---------------------------------------------------------------------------
#define TILE_B  (128 * RSW * 2)          // 18432 bytes per tile
#define SM_A0   0
#define SM_A1   (TILE_B)
#define SM_B0   (2 * TILE_B)
#define SM_B1   (3 * TILE_B)
#define SM_TOTAL (4 * TILE_B)            // 73728

__global__ __launch_bounds__(256) void kan_gemm_kernel()
{
    extern __shared__ char smem[];
    const uint32_t sb = smem_u32(smem);
    const int t = threadIdx.x;

    const int m0 = blockIdx.x * MT;
    const int n0 = blockIdx.y * NT;
    const int z  = blockIdx.z;
    const int kbase0 = z * KLOCAL;

    const int wid = t >> 5;
    const int wm  = wid & 1;        // 0..1 -> 64-row slab
    const int wn  = wid >> 1;       // 0..3 -> 32-col slab

    const uint32_t aoff[2] = {SM_A0, SM_A1};
    const uint32_t boff[2] = {SM_B0, SM_B1};

    // chunk loader: 128 rows x 64 bf16 (8x16B per row), 1024 units / 256 thr
    auto load_tile = [&](const __nv_bfloat16* gbase, int row0, int kb, uint32_t so) {
        #pragma unroll
        for (int it = 0; it < 4; it++) {
            const int unit = t + it * 256;
            const int r    = unit >> 3;
            const int c16  = unit & 7;
            const __nv_bfloat16* src = gbase + (size_t)(row0 + r) * KTOT + kb + c16 * 8;
            cp_async16(sb + so + r * (RSW * 2) + c16 * 16, src);
        }
        asm volatile("cp.async.commit_group;" ::: "memory");
    };

    wmma::fragment<wmma::accumulator, 16, 16, 16, float> cf[4][2];
    #pragma unroll
    for (int mi = 0; mi < 4; mi++)
        #pragma unroll
        for (int ni = 0; ni < 2; ni++)
            wmma::fill_fragment(cf[mi][ni], 0.0f);

    // prologue: chunk 0 -> slot 0
    load_tile(g_Bmat,  m0, kbase0, aoff[0]);
    load_tile(g_coefT, n0, kbase0, boff[0]);

    for (int c = 0; c < NCHUNK; c++) {
        const int slot = c & 1;
        if (c + 1 < NCHUNK) {
            const int kb = kbase0 + (c + 1) * KC;
            load_tile(g_Bmat,  m0, kb, aoff[(c + 1) & 1]);
            load_tile(g_coefT, n0, kb, boff[(c + 1) & 1]);
            asm volatile("cp.async.wait_group 1;" ::: "memory");
        } else {
            asm volatile("cp.async.wait_group 0;" ::: "memory");
        }
        __syncthreads();

        const __nv_bfloat16* At = (const __nv_bfloat16*)(smem + aoff[slot]);
        const __nv_bfloat16* Bt = (const __nv_bfloat16*)(smem + boff[slot]);

        #pragma unroll
        for (int ks = 0; ks < KC / 16; ks++) {
            wmma::fragment<wmma::matrix_a, 16, 16, 16, __nv_bfloat16, wmma::row_major> af[4];
            wmma::fragment<wmma::matrix_b, 16, 16, 16, __nv_bfloat16, wmma::col_major> bf[2];
            #pragma unroll
            for (int mi = 0; mi < 4; mi++)
                wmma::load_matrix_sync(af[mi],
                    At + (wm * 64 + mi * 16) * RSW + ks * 16, RSW);
            #pragma unroll
            for (int ni = 0; ni < 2; ni++)
                wmma::load_matrix_sync(bf[ni],
                    Bt + (wn * 32 + ni * 16) * RSW + ks * 16, RSW);
            #pragma unroll
            for (int mi = 0; mi < 4; mi++)
                #pragma unroll
                for (int ni = 0; ni < 2; ni++)
                    wmma::mma_sync(cf[mi][ni], af[mi], bf[ni], cf[mi][ni]);
        }
        __syncthreads();
    }

    // epilogue: store warp tiles straight to partials (row-major, ldm=OUT_DIM)
    float* pbase = g_part + (size_t)z * (BATCH * OUT_DIM)
                 + (size_t)(m0 + wm * 64) * OUT_DIM + n0 + wn * 32;
    #pragma unroll
    for (int mi = 0; mi < 4; mi++)
        #pragma unroll
        for (int ni = 0; ni < 2; ni++)
            wmma::store_matrix_sync(pbase + (size_t)(mi * 16) * OUT_DIM + ni * 16,
                                    cf[mi][ni], OUT_DIM, wmma::mem_row_major);
}

// ---------------------------------------------------------------------------
// Kernel 4: deterministic reduce over KSPLIT partials.
// ---------------------------------------------------------------------------
__global__ __launch_bounds__(256) void kan_reduce_kernel(float* __restrict__ out)
{
    const int idx = blockIdx.x * 256 + threadIdx.x;
    float s = 0.0f;
    #pragma unroll
    for (int sp = 0; sp < KSPLIT; sp++)
        s += g_part[(size_t)sp * (BATCH * OUT_DIM) + idx];
    out[idx] = s;
}

// ---------------------------------------------------------------------------
// Launch. Inputs: x, grid, coef, scale_sp, mask. Output fp32 [BATCH, OUT_DIM].
// ---------------------------------------------------------------------------
extern "C" void kernel_launch(void* const* d_in, const int* in_sizes, int n_in,
                              void* d_out, int out_size)
{
    const float* x        = (const float*)d_in[0];
    const float* grid     = (const float*)d_in[1];
    const float* coef     = (const float*)d_in[2];
    const float* scale_sp = (const float*)d_in[3];
    const float* mask     = (const float*)d_in[4];
    float* out = (float*)d_out;

    cudaFuncSetAttribute(kan_gemm_kernel,
                         cudaFuncAttributeMaxDynamicSharedMemorySize, SM_TOTAL);

    dim3 gp(IN_DIM / 32, BATCH / 8);
    kan_prep_kernel<<<gp, 256>>>(x, grid);

    dim3 gf(IN_DIM / 16, OUT_DIM / 32);
    kan_fold_kernel<<<gf, 256>>>(coef, scale_sp, mask);

    dim3 gg(BATCH / MT, OUT_DIM / NT, KSPLIT);
    kan_gemm_kernel<<<gg, 256, SM_TOTAL>>>();

    kan_reduce_kernel<<<(BATCH * OUT_DIM) / 256, 256>>>(out);
}

// round 8
// speedup vs baseline: 2.1946x; 1.1614x over previous
#include <cuda_runtime.h>
#include <cuda_bf16.h>
#include <mma.h>
#include <math.h>
#include <stdint.h>

using namespace nvcuda;

// Problem constants
#define BATCH   256
#define IN_DIM  512
#define OUT_DIM 512
#define KORD    3
#define GN      23
#define NB      19

// GEMM geometry
#define KSLOT   24
#define KTOT    (IN_DIM * KSLOT)        // 12288
#define MT      128
#define NT      128
#define KSPLIT  16
#define KLOCAL  (KTOT / KSPLIT)         // 768
#define KC      64
#define NCHUNK  (KLOCAL / KC)           // 12
#define RSW     72                      // smem row stride in bf16 (144B)
#define NSTAGE  4

// Static device scratch
__device__ __nv_bfloat16 g_Bmat [BATCH * KTOT];
__device__ __nv_bfloat16 g_coefT[OUT_DIM * KTOT];
__device__ float         g_part [KSPLIT * BATCH * OUT_DIM];

__device__ __forceinline__ uint32_t smem_u32(const void* p) {
    uint32_t a;
    asm("{ .reg .u64 t; cvta.to.shared.u64 t, %1; cvt.u32.u64 %0, t; }"
        : "=r"(a) : "l"(p));
    return a;
}
__device__ __forceinline__ void cp_async16(uint32_t dst, const void* src) {
    asm volatile("cp.async.cg.shared.global [%0], [%1], 16;" :: "r"(dst), "l"(src));
}

// ---------------------------------------------------------------------------
// Fused kernel A: blocks [0,512) = prep, [512,1024) = fold.
// ---------------------------------------------------------------------------
__device__ void prep_impl(unsigned char* sbuf, int bx,
                          const float* __restrict__ x,
                          const float* __restrict__ grid)
{
    float (*Gs)[25]     = (float(*)[25])sbuf;          // 32*25*4 = 3200 B
    float (*rowbuf)[25] = (float(*)[25])(sbuf + 3200); // 256*25*4 = 25600 B

    const int i0 = (bx & 15) * 32;
    const int b0 = (bx >> 4) * 8;
    const int t    = threadIdx.x;
    const int lane = t & 31;   // i_local
    const int row  = t >> 5;   // b_local

    for (int k = t; k < 32 * GN; k += 256) {
        const int r = k / GN, c = k - r * GN;
        Gs[r][c] = grid[(size_t)(i0 + r) * GN + c];
    }
    const float xv = x[(size_t)(b0 + row) * IN_DIM + i0 + lane];
    __syncthreads();

    const float* G = Gs[lane];
    const float base = xv / (1.0f + __expf(-xv));

    // fast interval index + comparison fixup (matches reference semantics)
    int m = -1;
    if (xv >= G[0] && xv < G[GN - 1]) {
        m = (int)((xv - G[0]) * __frcp_rn(G[1] - G[0]));
        if (m < 0) m = 0;
        if (m > GN - 2) m = GN - 2;
        while (m > 0 && xv < G[m]) --m;
        while (m < GN - 2 && xv >= G[m + 1]) ++m;
    }

    float bv0 = 0.f, bv1 = 0.f, bv2 = 0.f, bv3 = 0.f;
    int j = 0;
    if (m >= 0) {
        auto gg = [&](int idx) -> float {
            idx = idx < 0 ? 0 : (idx > GN - 1 ? GN - 1 : idx);
            return G[idx];
        };
        // de Boor partition-of-unity: bv[s] = B_{m-3+s}^3(x)
        float bv[4]; float lft[4], rgt[4];
        bv[0] = 1.0f;
        #pragma unroll
        for (int kk = 1; kk <= KORD; kk++) {
            lft[kk] = xv - gg(m + 1 - kk);
            rgt[kk] = gg(m + kk) - xv;
            float saved = 0.0f;
            #pragma unroll
            for (int r = 0; r < KORD; r++) {
                if (r >= kk) break;
                const float temp = bv[r] / (rgt[r + 1] + lft[kk - r]);
                bv[r] = saved + rgt[r + 1] * temp;
                saved = lft[kk - r] * temp;
            }
            bv[kk] = saved;
        }
        // window & validity: global basis r = m-3+s must lie in [0, NB-1]
        j = m - KORD;
        if (j < 0) j = 0;
        if (j > NB - 4) j = NB - 4;
        float w[4];
        #pragma unroll
        for (int tt = 0; tt < 4; tt++) {
            const int r = j + tt;
            const bool valid = (r >= m - KORD) && (r <= m) && (r >= 0) && (r <= NB - 1);
            w[tt] = valid ? bv[r - (m - KORD)] : 0.0f;
        }
        bv0 = w[0]; bv1 = w[1]; bv2 = w[2]; bv3 = w[3];
    }

    const float hi = __bfloat162float(__float2bfloat16(base));
    const float lo = base - hi;

    float* rb = rowbuf[t];
    #pragma unroll
    for (int s = 0; s < 19; s++) rb[s] = 0.0f;
    rb[j] = bv0; rb[j + 1] = bv1; rb[j + 2] = bv2; rb[j + 3] = bv3;
    rb[19] = 0.0f; rb[20] = base; rb[21] = lo; rb[22] = 0.0f; rb[23] = 0.0f;

    unsigned uw[12];
    #pragma unroll
    for (int p = 0; p < 12; p++) {
        asm("cvt.rn.bf16x2.f32 %0, %1, %2;"
            : "=r"(uw[p]) : "f"(rb[2 * p + 1]), "f"(rb[2 * p]));
    }
    uint4* dst = (uint4*)((char*)g_Bmat + (size_t)(b0 + row) * (KTOT * 2)
                          + (size_t)(i0 + lane) * (KSLOT * 2));
    dst[0] = make_uint4(uw[0], uw[1], uw[2],  uw[3]);
    dst[1] = make_uint4(uw[4], uw[5], uw[6],  uw[7]);
    dst[2] = make_uint4(uw[8], uw[9], uw[10], uw[11]);
}

__device__ void fold_impl(unsigned char* sbuf, int bx,
                          const float* __restrict__ coef,
                          const float* __restrict__ scale_sp,
                          const float* __restrict__ mask)
{
    float* msc = (float*)sbuf;                                   // 2048 B
    __nv_bfloat16 (*T)[16 * KSLOT] =
        (__nv_bfloat16(*)[16 * KSLOT])(sbuf + 2048);             // 24576 B

    const int i0 = (bx & 31) * 16;
    const int o0 = (bx >> 5) * 32;
    const int t  = threadIdx.x;

    #pragma unroll
    for (int rr = 0; rr < 2; rr++) {
        const int id = t + rr * 256;
        const int il = id >> 5, ol = id & 31;
        const size_t io = (size_t)(i0 + il) * OUT_DIM + o0 + ol;
        const float mk = mask[io];
        msc[id] = mk * scale_sp[io];
        const __nv_bfloat16 mb = __float2bfloat16(mk);
        const __nv_bfloat16 zb = __float2bfloat16(0.0f);
        T[ol][il * KSLOT + 19] = zb;
        T[ol][il * KSLOT + 20] = mb;
        T[ol][il * KSLOT + 21] = mb;
        T[ol][il * KSLOT + 22] = zb;
        T[ol][il * KSLOT + 23] = zb;
    }
    __syncthreads();

    #pragma unroll
    for (int k = 0; k < 38; k++) {
        const int lin = t + k * 256;            // < 9728 exactly
        const int il  = lin / 608;
        const int rem = lin - il * 608;
        const int ol  = rem / NB;
        const int g   = rem - ol * NB;
        const float v = coef[(size_t)(i0 + il) * (OUT_DIM * NB) + o0 * NB + rem]
                        * msc[il * 32 + ol];
        T[ol][il * KSLOT + g] = __float2bfloat16(v);
    }
    __syncthreads();

    const int ol  = t >> 3;
    const int sub = t & 7;
    uint4* dst = (uint4*)((char*)g_coefT + (size_t)(o0 + ol) * (KTOT * 2)
                          + (size_t)i0 * (KSLOT * 2));
    const uint4* src = (const uint4*)&T[ol][0];
    #pragma unroll
    for (int k = 0; k < 6; k++) dst[sub + k * 8] = src[sub + k * 8];
}

__global__ __launch_bounds__(256) void kan_prep_fold_kernel(
    const float* __restrict__ x, const float* __restrict__ grid,
    const float* __restrict__ coef, const float* __restrict__ scale_sp,
    const float* __restrict__ mask)
{
    __shared__ __align__(16) unsigned char sbuf[28800];
    const int bx = blockIdx.x;
    if (bx < 512) prep_impl(sbuf, bx, x, grid);
    else          fold_impl(sbuf, bx - 512, coef, scale_sp, mask);
}

// ---------------------------------------------------------------------------
// Kernel B: bf16 wmma GEMM, 4-stage cp.async pipeline, K-split.
// grid (2, 4, 16); 256 threads = 8 warps (2M x 4N), warp tile 64x32.
// ---------------------------------------------------------------------------
#define TILE_B   (128 * RSW * 2)                 // 18432 B per matrix tile
#define STAGE_B  (2 * TILE_B)                    // A + B per stage
#define SM_TOTAL (NSTAGE * STAGE_B)              // 147456 B

__global__ __launch_bounds__(256) void kan_gemm_kernel()
{
    extern __shared__ char smem[];
    const uint32_t sb = smem_u32(smem);
    const int t = threadIdx.x;

    const int m0 = blockIdx.x * MT;
    const int n0 = blockIdx.y * NT;
    const int kbase0 = blockIdx.z * KLOCAL;

    const int wid = t >> 5;
    const int wm  = wid & 1;
    const int wn  = wid >> 1;

    // one commit group per chunk: A tile then B tile (2048 x 16B units)
    auto load_chunk = [&](int c, int stage) {
        const int kb = kbase0 + c * KC;
        const uint32_t so = sb + stage * STAGE_B;
        #pragma unroll
        for (int it = 0; it < 4; it++) {
            const int unit = t + it * 256;
            const int r = unit >> 3, c16 = unit & 7;
            cp_async16(so + r * (RSW * 2) + c16 * 16,
                       g_Bmat + (size_t)(m0 + r) * KTOT + kb + c16 * 8);
        }
        #pragma unroll
        for (int it = 0; it < 4; it++) {
            const int unit = t + it * 256;
            const int r = unit >> 3, c16 = unit & 7;
            cp_async16(so + TILE_B + r * (RSW * 2) + c16 * 16,
                       g_coefT + (size_t)(n0 + r) * KTOT + kb + c16 * 8);
        }
        asm volatile("cp.async.commit_group;" ::: "memory");
    };

    wmma::fragment<wmma::accumulator, 16, 16, 16, float> cf[4][2];
    #pragma unroll
    for (int mi = 0; mi < 4; mi++)
        #pragma unroll
        for (int ni = 0; ni < 2; ni++)
            wmma::fill_fragment(cf[mi][ni], 0.0f);

    // prologue: 3 chunks in flight
    load_chunk(0, 0);
    load_chunk(1, 1);
    load_chunk(2, 2);

    for (int c = 0; c < NCHUNK; c++) {
        const int stage = c & (NSTAGE - 1);
        if (c + 3 < NCHUNK) {
            load_chunk(c + 3, (c + 3) & (NSTAGE - 1));
            asm volatile("cp.async.wait_group 3;" ::: "memory");
        } else if (c == NCHUNK - 3) {
            asm volatile("cp.async.wait_group 2;" ::: "memory");
        } else if (c == NCHUNK - 2) {
            asm volatile("cp.async.wait_group 1;" ::: "memory");
        } else {
            asm volatile("cp.async.wait_group 0;" ::: "memory");
        }
        __syncthreads();

        const __nv_bfloat16* At = (const __nv_bfloat16*)(smem + stage * STAGE_B);
        const __nv_bfloat16* Bt = (const __nv_bfloat16*)(smem + stage * STAGE_B + TILE_B);

        #pragma unroll
        for (int ks = 0; ks < KC / 16; ks++) {
            wmma::fragment<wmma::matrix_a, 16, 16, 16, __nv_bfloat16, wmma::row_major> af[4];
            wmma::fragment<wmma::matrix_b, 16, 16, 16, __nv_bfloat16, wmma::col_major> bf[2];
            #pragma unroll
            for (int mi = 0; mi < 4; mi++)
                wmma::load_matrix_sync(af[mi], At + (wm * 64 + mi * 16) * RSW + ks * 16, RSW);
            #pragma unroll
            for (int ni = 0; ni < 2; ni++)
                wmma::load_matrix_sync(bf[ni], Bt + (wn * 32 + ni * 16) * RSW + ks * 16, RSW);
            #pragma unroll
            for (int mi = 0; mi < 4; mi++)
                #pragma unroll
                for (int ni = 0; ni < 2; ni++)
                    wmma::mma_sync(cf[mi][ni], af[mi], bf[ni], cf[mi][ni]);
        }
        __syncthreads();
    }

    float* pbase = g_part + (size_t)blockIdx.z * (BATCH * OUT_DIM)
                 + (size_t)(m0 + wm * 64) * OUT_DIM + n0 + wn * 32;
    #pragma unroll
    for (int mi = 0; mi < 4; mi++)
        #pragma unroll
        for (int ni = 0; ni < 2; ni++)
            wmma::store_matrix_sync(pbase + (size_t)(mi * 16) * OUT_DIM + ni * 16,
                                    cf[mi][ni], OUT_DIM, wmma::mem_row_major);
}

// ---------------------------------------------------------------------------
// Kernel C: deterministic reduce over KSPLIT partials (float2 lanes).
// ---------------------------------------------------------------------------
__global__ __launch_bounds__(256) void kan_reduce_kernel(float* __restrict__ out)
{
    const int idx = blockIdx.x * 256 + threadIdx.x;     // 65536 float2 lanes
    const float2* p = (const float2*)g_part;
    float sx = 0.0f, sy = 0.0f;
    #pragma unroll
    for (int sp = 0; sp < KSPLIT; sp++) {
        const float2 v = p[(size_t)sp * (BATCH * OUT_DIM / 2) + idx];
        sx += v.x; sy += v.y;
    }
    ((float2*)out)[idx] = make_float2(sx, sy);
}

// ---------------------------------------------------------------------------
// Launch. Inputs: x, grid, coef, scale_sp, mask. Output fp32 [BATCH, OUT_DIM].
// ---------------------------------------------------------------------------
extern "C" void kernel_launch(void* const* d_in, const int* in_sizes, int n_in,
                              void* d_out, int out_size)
{
    const float* x        = (const float*)d_in[0];
    const float* grid     = (const float*)d_in[1];
    const float* coef     = (const float*)d_in[2];
    const float* scale_sp = (const float*)d_in[3];
    const float* mask     = (const float*)d_in[4];
    float* out = (float*)d_out;

    cudaFuncSetAttribute(kan_gemm_kernel,
                         cudaFuncAttributeMaxDynamicSharedMemorySize, SM_TOTAL);

    kan_prep_fold_kernel<<<1024, 256>>>(x, grid, coef, scale_sp, mask);

    dim3 gg(BATCH / MT, OUT_DIM / NT, KSPLIT);
    kan_gemm_kernel<<<gg, 256, SM_TOTAL>>>();

    kan_reduce_kernel<<<(BATCH * OUT_DIM / 2) / 256, 256>>>(out);
}